// round 1
// baseline (speedup 1.0000x reference)
#include <cuda_runtime.h>

// ---------------------------------------------------------------------------
// Sparse 3D CNN pipeline, fp32 baseline.
// conv = sequential-per-offset gather-GEMM-scatter (conflict-free RMW within
// one offset since each output row appears at most once per offset).
// ---------------------------------------------------------------------------

// Scratch (device globals; allocation-free rule)
__device__ float g_bufA[32768 * 512];
__device__ float g_bufB[32768 * 512];
__device__ float g_sum[512];
__device__ float g_sumsq[512];
__device__ float g_coefA[512];
__device__ float g_coefB[512];
__device__ int   g_cnt1[27];
__device__ int   g_cnt2[27];
__device__ float g_glob[8 * 512];
__device__ float g_fcb1[8 * 4096];
__device__ float g_fcb2[8 * 4096];

// ---------------------------------------------------------------------------
__global__ void k_zero(float* __restrict__ p, int n) {
    int i = blockIdx.x * blockDim.x + threadIdx.x;
    int stride = gridDim.x * blockDim.x;
    for (; i < n; i += stride) p[i] = 0.0f;
}

// one block per kernel-offset k: count non-sentinel entries (padding uses out==sentinel)
__global__ void k_count(const int* __restrict__ out_idx, int P, int sentinel,
                        int* __restrict__ counts) {
    int k = blockIdx.x;
    const int* o = out_idx + (long)k * P;
    int c = 0;
    for (int p = threadIdx.x; p < P; p += blockDim.x) c += (o[p] != sentinel);
    __shared__ int sm[256];
    sm[threadIdx.x] = c;
    __syncthreads();
    for (int s = 128; s > 0; s >>= 1) {
        if (threadIdx.x < s) sm[threadIdx.x] += sm[threadIdx.x + s];
        __syncthreads();
    }
    if (threadIdx.x == 0) counts[k] = sm[0];
}

// ---------------------------------------------------------------------------
// Gather-GEMM-scatter for ONE kernel offset k.
// Tile: 128 pairs x 64 output channels, 256 threads, 8x4 per thread.
// out[out_idx[p]] += x[in_idx[p]] @ Wk  (plain RMW; rows unique within one k).
// ---------------------------------------------------------------------------
#define AS_LD 132   // 128 + pad (multiple of 4 -> float4-aligned reads)
#define BS_LD 68    // 64 + pad

__global__ __launch_bounds__(256)
void k_conv_gemm(const float* __restrict__ x, const float* __restrict__ Wk,
                 const int* __restrict__ in_idx, const int* __restrict__ out_idx,
                 const int* __restrict__ counts, int k, int P, int K, int CO,
                 float* __restrict__ out) {
    int count = counts[k];
    int row0 = blockIdx.x * 128;
    if (row0 >= count) return;
    int col0 = blockIdx.y * 64;

    __shared__ __align__(16) float As[16 * AS_LD];
    __shared__ __align__(16) float Bs[16 * BS_LD];
    __shared__ int rs[128];
    __shared__ int os[128];

    int tid = threadIdx.x;
    if (tid < 128) {
        int p = row0 + tid;
        bool valid = p < count;
        rs[tid] = valid ? in_idx[(long)k * P + p] : -1;
        os[tid] = valid ? out_idx[(long)k * P + p] : -1;
    }
    __syncthreads();

    int ty = tid >> 4;        // 0..15 -> rows ty*8..ty*8+7
    int tx = tid & 15;        // 0..15 -> cols tx*4..tx*4+3

    float acc[8][4];
#pragma unroll
    for (int i = 0; i < 8; i++)
#pragma unroll
        for (int j = 0; j < 4; j++) acc[i][j] = 0.0f;

    int lrow = tid >> 2;          // 0..63
    int lk4  = (tid & 3) * 4;     // 0,4,8,12
    int brow = tid >> 4;          // 0..15
    int bc4  = (tid & 15) * 4;    // 0..60

    for (int k0 = 0; k0 < K; k0 += 16) {
        // gather x rows into As[kc][row]
#pragma unroll
        for (int pass = 0; pass < 2; pass++) {
            int row = lrow + pass * 64;
            int r = rs[row];
            float4 v = make_float4(0.f, 0.f, 0.f, 0.f);
            if (r >= 0) v = *(const float4*)&x[(long)r * K + k0 + lk4];
            As[(lk4 + 0) * AS_LD + row] = v.x;
            As[(lk4 + 1) * AS_LD + row] = v.y;
            As[(lk4 + 2) * AS_LD + row] = v.z;
            As[(lk4 + 3) * AS_LD + row] = v.w;
        }
        // weights into Bs[kc][col]
        float4 wv = *(const float4*)&Wk[(long)(k0 + brow) * CO + col0 + bc4];
        *(float4*)&Bs[brow * BS_LD + bc4] = wv;
        __syncthreads();

#pragma unroll
        for (int kk = 0; kk < 16; kk++) {
            float4 b  = *(const float4*)&Bs[kk * BS_LD + tx * 4];
            float4 a0 = *(const float4*)&As[kk * AS_LD + ty * 8];
            float4 a1 = *(const float4*)&As[kk * AS_LD + ty * 8 + 4];
            float a[8] = {a0.x, a0.y, a0.z, a0.w, a1.x, a1.y, a1.z, a1.w};
            float bb[4] = {b.x, b.y, b.z, b.w};
#pragma unroll
            for (int i = 0; i < 8; i++)
#pragma unroll
                for (int j = 0; j < 4; j++) acc[i][j] += a[i] * bb[j];
        }
        __syncthreads();
    }

    // scatter-add (unique rows within this k -> plain RMW)
#pragma unroll
    for (int i = 0; i < 8; i++) {
        int o = os[ty * 8 + i];
        if (o >= 0) {
            float4* po = (float4*)&out[(long)o * CO + col0 + tx * 4];
            float4 cur = *po;
            cur.x += acc[i][0];
            cur.y += acc[i][1];
            cur.z += acc[i][2];
            cur.w += acc[i][3];
            *po = cur;
        }
    }
}

// ---------------------------------------------------------------------------
// BN (training mode, biased variance) + ReLU
// ---------------------------------------------------------------------------
__global__ void k_bn_zero() {
    int c = threadIdx.x;
    if (c < 512) { g_sum[c] = 0.0f; g_sumsq[c] = 0.0f; }
}

__global__ void k_bn_stats(const float* __restrict__ x, int n) {
    int c = threadIdx.x;                 // 256 threads -> channels c, c+256
    int r0 = blockIdx.x * 128;
    int rend = min(r0 + 128, n);
    float s0 = 0.f, s20 = 0.f, s1 = 0.f, s21 = 0.f;
    for (int r = r0; r < rend; r++) {
        float v0 = x[(long)r * 512 + c];
        float v1 = x[(long)r * 512 + c + 256];
        s0 += v0; s20 += v0 * v0;
        s1 += v1; s21 += v1 * v1;
    }
    atomicAdd(&g_sum[c], s0);
    atomicAdd(&g_sumsq[c], s20);
    atomicAdd(&g_sum[c + 256], s1);
    atomicAdd(&g_sumsq[c + 256], s21);
}

__global__ void k_bn_coef(const float* __restrict__ gamma,
                          const float* __restrict__ beta, float inv_n) {
    int c = threadIdx.x;
    float mu = g_sum[c] * inv_n;
    float var = g_sumsq[c] * inv_n - mu * mu;
    float a = gamma[c] * rsqrtf(var + 1e-5f);
    g_coefA[c] = a;
    g_coefB[c] = beta[c] - mu * a;
}

__global__ void k_bn_apply(float* __restrict__ x, int total4) {
    int i = blockIdx.x * blockDim.x + threadIdx.x;
    int stride = gridDim.x * blockDim.x;
    for (; i < total4; i += stride) {
        float4 v = ((float4*)x)[i];
        int c = (i * 4) & 511;
        float4 a  = *(const float4*)&g_coefA[c];
        float4 bb = *(const float4*)&g_coefB[c];
        v.x = fmaxf(v.x * a.x + bb.x, 0.f);
        v.y = fmaxf(v.y * a.y + bb.y, 0.f);
        v.z = fmaxf(v.z * a.z + bb.z, 0.f);
        v.w = fmaxf(v.w * a.w + bb.w, 0.f);
        ((float4*)x)[i] = v;
    }
}

// ---------------------------------------------------------------------------
// segment max. Inputs are post-ReLU (>=0), output pre-zeroed, so signed-int
// atomicMax on the float bit pattern is order-preserving.
// ---------------------------------------------------------------------------
__global__ void k_pool_max(const float* __restrict__ x, const int* __restrict__ idx,
                           float* __restrict__ out, int n_in) {
    long total = (long)n_in * 512;
    long i = (long)blockIdx.x * blockDim.x + threadIdx.x;
    long stride = (long)gridDim.x * blockDim.x;
    for (; i < total; i += stride) {
        int r = (int)(i >> 9);
        int c = (int)(i & 511);
        float v = x[i];
        atomicMax((int*)&out[(long)idx[r] * 512 + c], __float_as_int(v));
    }
}

// ---------------------------------------------------------------------------
__global__ void k_fc(const float* __restrict__ x, const float* __restrict__ w,
                     const float* __restrict__ bias, float* __restrict__ y,
                     int Bn, int K, int N, int do_relu) {
    int i = blockIdx.x * blockDim.x + threadIdx.x;
    if (i >= Bn * N) return;
    int b = i / N, j = i % N;
    float s = bias[j];
    const float* xr = x + (long)b * K;
    for (int k = 0; k < K; k++) s += xr[k] * w[(long)k * N + j];
    y[i] = do_relu ? fmaxf(s, 0.f) : s;
}

// ---------------------------------------------------------------------------
extern "C" void kernel_launch(void* const* d_in, const int* in_sizes, int n_in,
                              void* d_out, int out_size) {
    const float* feats    = (const float*)d_in[0];
    const float* w[6]     = {(const float*)d_in[1], (const float*)d_in[2],
                             (const float*)d_in[3], (const float*)d_in[4],
                             (const float*)d_in[5], (const float*)d_in[6]};
    const float* bn_gamma = (const float*)d_in[7];
    const float* bn_beta  = (const float*)d_in[8];
    const float* fc1_w = (const float*)d_in[9];
    const float* fc1_b = (const float*)d_in[10];
    const float* fc2_w = (const float*)d_in[11];
    const float* fc2_b = (const float*)d_in[12];
    const float* fc3_w = (const float*)d_in[13];
    const float* fc3_b = (const float*)d_in[14];
    const int* map1_in  = (const int*)d_in[15];
    const int* map1_out = (const int*)d_in[16];
    const int* map2_in  = (const int*)d_in[17];
    const int* map2_out = (const int*)d_in[18];
    const int* pool1_idx = (const int*)d_in[19];
    const int* pool2_idx = (const int*)d_in[20];
    const int* batch_idx = (const int*)d_in[21];

    int n1 = in_sizes[19];
    int n2 = in_sizes[20];
    int n3 = in_sizes[21];
    int P1 = in_sizes[15] / 27;
    int P2 = in_sizes[17] / 27;

    float *bufA, *bufB, *glob, *fcb1, *fcb2;
    int *cnt1, *cnt2;
    cudaGetSymbolAddress((void**)&bufA, g_bufA);
    cudaGetSymbolAddress((void**)&bufB, g_bufB);
    cudaGetSymbolAddress((void**)&glob, g_glob);
    cudaGetSymbolAddress((void**)&fcb1, g_fcb1);
    cudaGetSymbolAddress((void**)&fcb2, g_fcb2);
    cudaGetSymbolAddress((void**)&cnt1, g_cnt1);
    cudaGetSymbolAddress((void**)&cnt2, g_cnt2);

    k_count<<<27, 256>>>(map1_out, P1, n1, cnt1);
    k_count<<<27, 256>>>(map2_out, P2, n2, cnt2);

    auto zero = [&](float* p, long n) {
        int blocks = (int)min((n + 255) / 256, (long)8192);
        k_zero<<<blocks, 256>>>(p, (int)n);
    };

    auto conv = [&](const float* xin, const float* Wc, int Kdim,
                    const int* m_in, const int* m_out, int* cnts, int P,
                    int n_out, float* out) {
        zero(out, (long)n_out * 512);
        dim3 grid((P + 127) / 128, 8);
        for (int k = 0; k < 27; k++) {
            k_conv_gemm<<<grid, 256>>>(xin, Wc + (long)k * Kdim * 512,
                                       m_in, m_out, cnts, k, P, Kdim, 512, out);
        }
    };

    auto bn = [&](float* xio, int n, int layer) {
        k_bn_zero<<<1, 512>>>();
        k_bn_stats<<<(n + 127) / 128, 256>>>(xio, n);
        k_bn_coef<<<1, 512>>>(bn_gamma + layer * 512, bn_beta + layer * 512,
                              1.0f / (float)n);
        int total4 = n * 128;  // n*512/4
        int blocks = min((total4 + 255) / 256, 8192);
        k_bn_apply<<<blocks, 256>>>(xio, total4);
    };

    // ---- level 1: three convs at n1 ----
    conv(feats, w[0], 256, map1_in, map1_out, cnt1, P1, n1, bufB);
    bn(bufB, n1, 0);
    conv(bufB, w[1], 512, map1_in, map1_out, cnt1, P1, n1, bufA);
    bn(bufA, n1, 1);
    conv(bufA, w[2], 512, map1_in, map1_out, cnt1, P1, n1, bufB);
    bn(bufB, n1, 2);

    // ---- pool1: n1 -> n2 ----
    zero(bufA, (long)n2 * 512);
    k_pool_max<<<4096, 256>>>(bufB, pool1_idx, bufA, n1);

    // ---- level 2: three convs at n2 ----
    conv(bufA, w[3], 512, map2_in, map2_out, cnt2, P2, n2, bufB);
    bn(bufB, n2, 3);
    conv(bufB, w[4], 512, map2_in, map2_out, cnt2, P2, n2, bufA);
    bn(bufA, n2, 4);
    conv(bufA, w[5], 512, map2_in, map2_out, cnt2, P2, n2, bufB);
    bn(bufB, n2, 5);

    // ---- pool2: n2 -> n3, then global batch max -> [8,512] ----
    zero(bufA, (long)n3 * 512);
    k_pool_max<<<2048, 256>>>(bufB, pool2_idx, bufA, n2);
    zero(glob, 8 * 512);
    k_pool_max<<<512, 256>>>(bufA, batch_idx, glob, n3);

    // ---- FC head ----
    k_fc<<<(8 * 4096 + 255) / 256, 256>>>(glob, fc1_w, fc1_b, fcb1, 8, 512, 4096, 1);
    k_fc<<<(8 * 4096 + 255) / 256, 256>>>(fcb1, fc2_w, fc2_b, fcb2, 8, 4096, 4096, 1);
    k_fc<<<2, 256>>>(fcb2, fc3_w, fc3_b, (float*)d_out, 8, 4096, 40, 0);
}

// round 2
// speedup vs baseline: 2.7416x; 2.7416x over previous
#include <cuda_runtime.h>

// ---------------------------------------------------------------------------
// Sparse 3D CNN pipeline. Round 2: tf32 tensor-core gather-GEMM-scatter,
// one launch per conv (grid.z = 27 offsets), atomicAdd scatter.
// ---------------------------------------------------------------------------

__device__ float g_bufA[32768 * 512];
__device__ float g_bufB[32768 * 512];
__device__ float g_sum[512];
__device__ float g_sumsq[512];
__device__ float g_coefA[512];
__device__ float g_coefB[512];
__device__ int   g_cnt1[27];
__device__ int   g_cnt2[27];
__device__ float g_glob[8 * 512];
__device__ float g_fcb1[8 * 4096];
__device__ float g_fcb2[8 * 4096];

// ---------------------------------------------------------------------------
__global__ void k_zero(float* __restrict__ p, int n) {
    int i = blockIdx.x * blockDim.x + threadIdx.x;
    int stride = gridDim.x * blockDim.x;
    for (; i < n; i += stride) p[i] = 0.0f;
}

__global__ void k_count(const int* __restrict__ out_idx, int P, int sentinel,
                        int* __restrict__ counts) {
    int k = blockIdx.x;
    const int* o = out_idx + (long)k * P;
    int c = 0;
    for (int p = threadIdx.x; p < P; p += blockDim.x) c += (o[p] != sentinel);
    __shared__ int sm[256];
    sm[threadIdx.x] = c;
    __syncthreads();
    for (int s = 128; s > 0; s >>= 1) {
        if (threadIdx.x < s) sm[threadIdx.x] += sm[threadIdx.x + s];
        __syncthreads();
    }
    if (threadIdx.x == 0) counts[k] = sm[0];
}

// ---------------------------------------------------------------------------
// tf32 MMA gather-GEMM-scatter. Block tile 128 pairs x 128 cols, BK=16.
// 8 warps: 2 (M) x 4 (N); each warp 64x32 via m16n8k8. Scatter = atomicAdd
// (offsets run concurrently via grid.z, so output rows collide across z).
// ---------------------------------------------------------------------------
#define BM 128
#define BN 128
#define BK 16
#define ALD 136   // smem leading dim (conflict-free frag reads, 16B aligned)

__device__ __forceinline__ unsigned f2tf(float f) {
    unsigned u;
    asm("cvt.rna.tf32.f32 %0, %1;" : "=r"(u) : "f"(f));
    return u;
}

__global__ __launch_bounds__(256, 2)
void k_conv_mma(const float* __restrict__ x, const float* __restrict__ W,
                const int* __restrict__ in_idx, const int* __restrict__ out_idx,
                const int* __restrict__ counts, int P, int K,
                float* __restrict__ out) {
    int koff = blockIdx.z;
    int count = counts[koff];
    int row0 = blockIdx.x * BM;
    if (row0 >= count) return;
    int col0 = blockIdx.y * BN;
    const float* Wk = W + (long)koff * K * 512;

    __shared__ unsigned As[BK * ALD];   // [kc][row], tf32 bit patterns
    __shared__ unsigned Bs[BK * ALD];   // [kc][col]
    __shared__ int rs[BM], os[BM];

    int tid = threadIdx.x;
    if (tid < BM) {
        int p = row0 + tid;
        bool v = p < count;
        rs[tid] = v ? in_idx[(long)koff * P + p] : -1;
        os[tid] = v ? out_idx[(long)koff * P + p] : -1;
    }
    __syncthreads();

    int warp = tid >> 5, lane = tid & 31;
    int wm = warp & 1;    // 0..1 -> rows wm*64
    int wn = warp >> 1;   // 0..3 -> cols wn*32

    float acc[4][4][4];
#pragma unroll
    for (int mt = 0; mt < 4; mt++)
#pragma unroll
        for (int nt = 0; nt < 4; nt++)
#pragma unroll
            for (int i = 0; i < 4; i++) acc[mt][nt][i] = 0.0f;

    // loader indices
    int arow = tid >> 1;              // 0..127
    int akk0 = (tid & 1) * 8;         // 0 or 8
    int bkc  = tid >> 4;              // 0..15
    int bc0  = (tid & 15) * 8;        // 0..120

    for (int k0 = 0; k0 < K; k0 += BK) {
        // ---- gather A: x[rs[row]][k0..k0+15] -> As[kc][row]
        {
            int r = rs[arow];
            float4 v0 = make_float4(0.f, 0.f, 0.f, 0.f), v1 = v0;
            if (r >= 0) {
                const float* xp = &x[(long)r * K + k0 + akk0];
                v0 = *(const float4*)xp;
                v1 = *(const float4*)(xp + 4);
            }
            As[(akk0 + 0) * ALD + arow] = f2tf(v0.x);
            As[(akk0 + 1) * ALD + arow] = f2tf(v0.y);
            As[(akk0 + 2) * ALD + arow] = f2tf(v0.z);
            As[(akk0 + 3) * ALD + arow] = f2tf(v0.w);
            As[(akk0 + 4) * ALD + arow] = f2tf(v1.x);
            As[(akk0 + 5) * ALD + arow] = f2tf(v1.y);
            As[(akk0 + 6) * ALD + arow] = f2tf(v1.z);
            As[(akk0 + 7) * ALD + arow] = f2tf(v1.w);
        }
        // ---- load B: Wk[k0+kc][col0+c] -> Bs[kc][c]
        {
            const float* wp = &Wk[(long)(k0 + bkc) * 512 + col0 + bc0];
            float4 v0 = *(const float4*)wp;
            float4 v1 = *(const float4*)(wp + 4);
            uint4 p0 = make_uint4(f2tf(v0.x), f2tf(v0.y), f2tf(v0.z), f2tf(v0.w));
            uint4 p1 = make_uint4(f2tf(v1.x), f2tf(v1.y), f2tf(v1.z), f2tf(v1.w));
            *(uint4*)&Bs[bkc * ALD + bc0] = p0;
            *(uint4*)&Bs[bkc * ALD + bc0 + 4] = p1;
        }
        __syncthreads();

#pragma unroll
        for (int ks = 0; ks < 2; ks++) {
            int kk = ks * 8;
            unsigned a[4][4];
            int lk = lane & 3, lr = lane >> 2;
#pragma unroll
            for (int mt = 0; mt < 4; mt++) {
                int rb = wm * 64 + mt * 16;
                a[mt][0] = As[(kk + lk) * ALD + rb + lr];
                a[mt][1] = As[(kk + lk) * ALD + rb + lr + 8];
                a[mt][2] = As[(kk + 4 + lk) * ALD + rb + lr];
                a[mt][3] = As[(kk + 4 + lk) * ALD + rb + lr + 8];
            }
            unsigned b[4][2];
#pragma unroll
            for (int nt = 0; nt < 4; nt++) {
                int cb = wn * 32 + nt * 8;
                b[nt][0] = Bs[(kk + lk) * ALD + cb + lr];
                b[nt][1] = Bs[(kk + 4 + lk) * ALD + cb + lr];
            }
#pragma unroll
            for (int mt = 0; mt < 4; mt++)
#pragma unroll
                for (int nt = 0; nt < 4; nt++) {
                    asm volatile(
                        "mma.sync.aligned.m16n8k8.row.col.f32.tf32.tf32.f32 "
                        "{%0,%1,%2,%3}, {%4,%5,%6,%7}, {%8,%9}, {%0,%1,%2,%3};"
                        : "+f"(acc[mt][nt][0]), "+f"(acc[mt][nt][1]),
                          "+f"(acc[mt][nt][2]), "+f"(acc[mt][nt][3])
                        : "r"(a[mt][0]), "r"(a[mt][1]), "r"(a[mt][2]), "r"(a[mt][3]),
                          "r"(b[nt][0]), "r"(b[nt][1]));
                }
        }
        __syncthreads();
    }

    // ---- scatter with atomicAdd (cross-offset collisions possible)
    int lr = lane >> 2, lc2 = (lane & 3) * 2;
#pragma unroll
    for (int mt = 0; mt < 4; mt++) {
        int r_lo = wm * 64 + mt * 16 + lr;
        int o_lo = os[r_lo];
        int o_hi = os[r_lo + 8];
#pragma unroll
        for (int nt = 0; nt < 4; nt++) {
            int c = col0 + wn * 32 + nt * 8 + lc2;
            if (o_lo >= 0) {
                atomicAdd(&out[(long)o_lo * 512 + c],     acc[mt][nt][0]);
                atomicAdd(&out[(long)o_lo * 512 + c + 1], acc[mt][nt][1]);
            }
            if (o_hi >= 0) {
                atomicAdd(&out[(long)o_hi * 512 + c],     acc[mt][nt][2]);
                atomicAdd(&out[(long)o_hi * 512 + c + 1], acc[mt][nt][3]);
            }
        }
    }
}

// ---------------------------------------------------------------------------
// BN (training mode, biased variance) + ReLU
// ---------------------------------------------------------------------------
__global__ void k_bn_zero() {
    int c = threadIdx.x;
    if (c < 512) { g_sum[c] = 0.0f; g_sumsq[c] = 0.0f; }
}

__global__ void k_bn_stats(const float* __restrict__ x, int n) {
    int c = threadIdx.x;
    int r0 = blockIdx.x * 128;
    int rend = min(r0 + 128, n);
    float s0 = 0.f, s20 = 0.f, s1 = 0.f, s21 = 0.f;
    for (int r = r0; r < rend; r++) {
        float v0 = x[(long)r * 512 + c];
        float v1 = x[(long)r * 512 + c + 256];
        s0 += v0; s20 += v0 * v0;
        s1 += v1; s21 += v1 * v1;
    }
    atomicAdd(&g_sum[c], s0);
    atomicAdd(&g_sumsq[c], s20);
    atomicAdd(&g_sum[c + 256], s1);
    atomicAdd(&g_sumsq[c + 256], s21);
}

__global__ void k_bn_coef(const float* __restrict__ gamma,
                          const float* __restrict__ beta, float inv_n) {
    int c = threadIdx.x;
    float mu = g_sum[c] * inv_n;
    float var = g_sumsq[c] * inv_n - mu * mu;
    float a = gamma[c] * rsqrtf(var + 1e-5f);
    g_coefA[c] = a;
    g_coefB[c] = beta[c] - mu * a;
}

__global__ void k_bn_apply(float* __restrict__ x, int total4) {
    int i = blockIdx.x * blockDim.x + threadIdx.x;
    int stride = gridDim.x * blockDim.x;
    for (; i < total4; i += stride) {
        float4 v = ((float4*)x)[i];
        int c = (i * 4) & 511;
        float4 a  = *(const float4*)&g_coefA[c];
        float4 bb = *(const float4*)&g_coefB[c];
        v.x = fmaxf(v.x * a.x + bb.x, 0.f);
        v.y = fmaxf(v.y * a.y + bb.y, 0.f);
        v.z = fmaxf(v.z * a.z + bb.z, 0.f);
        v.w = fmaxf(v.w * a.w + bb.w, 0.f);
        ((float4*)x)[i] = v;
    }
}

// ---------------------------------------------------------------------------
// segment max (inputs post-ReLU >=0; out pre-zeroed; int atomicMax on bits ok)
// ---------------------------------------------------------------------------
__global__ void k_pool_max(const float* __restrict__ x, const int* __restrict__ idx,
                           float* __restrict__ out, int n_in) {
    long total = (long)n_in * 512;
    long i = (long)blockIdx.x * blockDim.x + threadIdx.x;
    long stride = (long)gridDim.x * blockDim.x;
    for (; i < total; i += stride) {
        int r = (int)(i >> 9);
        int c = (int)(i & 511);
        float v = x[i];
        atomicMax((int*)&out[(long)idx[r] * 512 + c], __float_as_int(v));
    }
}

// ---------------------------------------------------------------------------
// FC: block computes 256 output cols for all 8 batch rows; x cached in smem.
// ---------------------------------------------------------------------------
__global__ __launch_bounds__(256)
void k_fc(const float* __restrict__ x, const float* __restrict__ w,
          const float* __restrict__ bias, float* __restrict__ y,
          int K, int N, int do_relu) {
    __shared__ float xs[8 * 512];
    int j = blockIdx.x * 256 + threadIdx.x;
    float acc[8];
#pragma unroll
    for (int b = 0; b < 8; b++) acc[b] = (j < N) ? bias[j] : 0.f;

    for (int k0 = 0; k0 < K; k0 += 512) {
        int chunk = min(512, K - k0);
        for (int i = threadIdx.x; i < 8 * chunk; i += 256) {
            int b = i / chunk, kk = i - b * chunk;
            xs[b * 512 + kk] = x[(long)b * K + k0 + kk];
        }
        __syncthreads();
        if (j < N) {
            for (int kk = 0; kk < chunk; kk++) {
                float wv = w[(long)(k0 + kk) * N + j];
#pragma unroll
                for (int b = 0; b < 8; b++) acc[b] += xs[b * 512 + kk] * wv;
            }
        }
        __syncthreads();
    }
    if (j < N) {
#pragma unroll
        for (int b = 0; b < 8; b++)
            y[(long)b * N + j] = do_relu ? fmaxf(acc[b], 0.f) : acc[b];
    }
}

// ---------------------------------------------------------------------------
extern "C" void kernel_launch(void* const* d_in, const int* in_sizes, int n_in,
                              void* d_out, int out_size) {
    const float* feats    = (const float*)d_in[0];
    const float* w[6]     = {(const float*)d_in[1], (const float*)d_in[2],
                             (const float*)d_in[3], (const float*)d_in[4],
                             (const float*)d_in[5], (const float*)d_in[6]};
    const float* bn_gamma = (const float*)d_in[7];
    const float* bn_beta  = (const float*)d_in[8];
    const float* fc1_w = (const float*)d_in[9];
    const float* fc1_b = (const float*)d_in[10];
    const float* fc2_w = (const float*)d_in[11];
    const float* fc2_b = (const float*)d_in[12];
    const float* fc3_w = (const float*)d_in[13];
    const float* fc3_b = (const float*)d_in[14];
    const int* map1_in  = (const int*)d_in[15];
    const int* map1_out = (const int*)d_in[16];
    const int* map2_in  = (const int*)d_in[17];
    const int* map2_out = (const int*)d_in[18];
    const int* pool1_idx = (const int*)d_in[19];
    const int* pool2_idx = (const int*)d_in[20];
    const int* batch_idx = (const int*)d_in[21];

    int n1 = in_sizes[19];
    int n2 = in_sizes[20];
    int n3 = in_sizes[21];
    int P1 = in_sizes[15] / 27;
    int P2 = in_sizes[17] / 27;

    float *bufA, *bufB, *glob, *fcb1, *fcb2;
    int *cnt1, *cnt2;
    cudaGetSymbolAddress((void**)&bufA, g_bufA);
    cudaGetSymbolAddress((void**)&bufB, g_bufB);
    cudaGetSymbolAddress((void**)&glob, g_glob);
    cudaGetSymbolAddress((void**)&fcb1, g_fcb1);
    cudaGetSymbolAddress((void**)&fcb2, g_fcb2);
    cudaGetSymbolAddress((void**)&cnt1, g_cnt1);
    cudaGetSymbolAddress((void**)&cnt2, g_cnt2);

    k_count<<<27, 256>>>(map1_out, P1, n1, cnt1);
    k_count<<<27, 256>>>(map2_out, P2, n2, cnt2);

    auto zero = [&](float* p, long n) {
        int blocks = (int)min((n + 255) / 256, (long)8192);
        k_zero<<<blocks, 256>>>(p, (int)n);
    };

    auto conv = [&](const float* xin, const float* Wc, int Kdim,
                    const int* m_in, const int* m_out, int* cnts, int P,
                    int n_out, float* out) {
        zero(out, (long)n_out * 512);
        dim3 grid((P + BM - 1) / BM, 512 / BN, 27);
        k_conv_mma<<<grid, 256>>>(xin, Wc, m_in, m_out, cnts, P, Kdim, out);
    };

    auto bn = [&](float* xio, int n, int layer) {
        k_bn_zero<<<1, 512>>>();
        k_bn_stats<<<(n + 127) / 128, 256>>>(xio, n);
        k_bn_coef<<<1, 512>>>(bn_gamma + layer * 512, bn_beta + layer * 512,
                              1.0f / (float)n);
        int total4 = n * 128;
        int blocks = min((total4 + 255) / 256, 8192);
        k_bn_apply<<<blocks, 256>>>(xio, total4);
    };

    // ---- level 1 ----
    conv(feats, w[0], 256, map1_in, map1_out, cnt1, P1, n1, bufB);
    bn(bufB, n1, 0);
    conv(bufB, w[1], 512, map1_in, map1_out, cnt1, P1, n1, bufA);
    bn(bufA, n1, 1);
    conv(bufA, w[2], 512, map1_in, map1_out, cnt1, P1, n1, bufB);
    bn(bufB, n1, 2);

    // ---- pool1 ----
    zero(bufA, (long)n2 * 512);
    k_pool_max<<<4096, 256>>>(bufB, pool1_idx, bufA, n1);

    // ---- level 2 ----
    conv(bufA, w[3], 512, map2_in, map2_out, cnt2, P2, n2, bufB);
    bn(bufB, n2, 3);
    conv(bufB, w[4], 512, map2_in, map2_out, cnt2, P2, n2, bufA);
    bn(bufA, n2, 4);
    conv(bufA, w[5], 512, map2_in, map2_out, cnt2, P2, n2, bufB);
    bn(bufB, n2, 5);

    // ---- pool2 + global max ----
    zero(bufA, (long)n3 * 512);
    k_pool_max<<<2048, 256>>>(bufB, pool2_idx, bufA, n2);
    zero(glob, 8 * 512);
    k_pool_max<<<512, 256>>>(bufA, batch_idx, glob, n3);

    // ---- FC head ----
    k_fc<<<16, 256>>>(glob, fc1_w, fc1_b, fcb1, 512, 4096, 1);
    k_fc<<<16, 256>>>(fcb1, fc2_w, fc2_b, fcb2, 4096, 4096, 1);
    k_fc<<<1, 256>>>(fcb2, fc3_w, fc3_b, (float*)d_out, 4096, 40, 0);
}